// round 6
// baseline (speedup 1.0000x reference)
#include <cuda_runtime.h>
#include <cuda_bf16.h>

#define DIM 64
#define NODES_MAX 100000

// Allocation-free scratch: accumulates h = x + sum(neighbor x).
__device__ float g_agg[(size_t)NODES_MAX * DIM];

// ---------------------------------------------------------------------------
// Packed fp32x2 helpers (Blackwell sm_100+; ptxas will not auto-fuse these).
// ---------------------------------------------------------------------------
__device__ __forceinline__ unsigned long long pack2(float lo, float hi) {
    unsigned long long r;
    asm("mov.b64 %0, {%1, %2};" : "=l"(r) : "f"(lo), "f"(hi));
    return r;
}
__device__ __forceinline__ void unpack2(unsigned long long v, float& lo, float& hi) {
    asm("mov.b64 {%0, %1}, %2;" : "=f"(lo), "=f"(hi) : "l"(v));
}
#define FMA2(d, a, b) asm("fma.rn.f32x2 %0, %1, %2, %0;" : "+l"(d) : "l"(a), "l"(b))

// ---------------------------------------------------------------------------
// Kernel 1: initialize accumulator with x (h starts at (1+eps)*x, eps=0).
// ---------------------------------------------------------------------------
__global__ void init_kernel(const float* __restrict__ x, int n4) {
    int i = blockIdx.x * blockDim.x + threadIdx.x;
    if (i < n4) {
        ((float4*)g_agg)[i] = ((const float4*)x)[i];
    }
}

// ---------------------------------------------------------------------------
// Kernel 2: edge scatter-add. 16 threads per edge, one float4 chunk each.
// x and agg are L2-resident (25.6 MB each); LTS-throughput bound.
// ---------------------------------------------------------------------------
__global__ void scatter_kernel(const float* __restrict__ x,
                               const int* __restrict__ src,
                               const int* __restrict__ dst,
                               int E) {
    long long g = (long long)blockIdx.x * blockDim.x + threadIdx.x;
    int e = (int)(g >> 4);
    int c = (int)(g & 15);
    if (e >= E) return;
    int s = __ldg(src + e);
    int d = __ldg(dst + e);
    float4 v = ((const float4*)x)[(long long)s * 16 + c];
    atomicAdd(((float4*)g_agg) + ((long long)d * 16 + c), v);
}

// ---------------------------------------------------------------------------
// Kernel 3: fused MLP per 64-node tile. 64 threads; each owns an
// 8-node x 8-col register tile held as f32x2 pairs (4 col-pairs).
// Per k-step: 2 LDS.128 (h, 8 nodes) + 2 LDS.128 (W, 8 cols = 4 pairs)
// feed 32 fma.rn.f32x2 (= 64 FMA): 1.0 B LDS per FMA, half the FFMA issues.
// Ws time-multiplexes W1 -> W2 at the layer boundary.
// ---------------------------------------------------------------------------
__global__ __launch_bounds__(64) void mlp_kernel(const float* __restrict__ x,
                                                 const float* __restrict__ W1,
                                                 const float* __restrict__ b1,
                                                 const float* __restrict__ W2,
                                                 const float* __restrict__ b2,
                                                 float* __restrict__ out,
                                                 int N) {
    __shared__ float Ws[64 * 64];
    __shared__ float b1s[64];
    __shared__ float b2s[64];
    __shared__ float hs[64 * 68];   // feature-major: hs[f * 68 + n]

    const int tid = threadIdx.x;

    for (int i = tid; i < 1024; i += 64)
        ((float4*)Ws)[i] = ((const float4*)W1)[i];
    b1s[tid] = b1[tid];
    b2s[tid] = b2[tid];

    const int node0 = blockIdx.x * 64;

    // Load h tile from g_agg, transposed to feature-major.
    for (int i = tid; i < 1024; i += 64) {
        int n  = i >> 4;
        int f4 = i & 15;
        int node = node0 + n;
        float4 v = (node < N) ? ((const float4*)g_agg)[(size_t)node * 16 + f4]
                              : make_float4(0.f, 0.f, 0.f, 0.f);
        int f = f4 * 4;
        hs[(f + 0) * 68 + n] = v.x;
        hs[(f + 1) * 68 + n] = v.y;
        hs[(f + 2) * 68 + n] = v.z;
        hs[(f + 3) * 68 + n] = v.w;
    }
    __syncthreads();

    const int tc = tid >> 3;   // 0..7 : cols  tc*8 .. tc*8+7 (4 f32x2 pairs)
    const int tn = tid & 7;    // 0..7 : nodes tn*8 .. tn*8+7

    unsigned long long acc[8][4];   // [node][col-pair]
    float av[8][8];                 // unpacked staging

    // ================= Layer 1: h1 = relu(h @ W1 + b1) =================
    {
        float4 ba = *(const float4*)&b1s[tc * 8];
        float4 bb = *(const float4*)&b1s[tc * 8 + 4];
        unsigned long long bp0 = pack2(ba.x, ba.y), bp1 = pack2(ba.z, ba.w);
        unsigned long long bp2 = pack2(bb.x, bb.y), bp3 = pack2(bb.z, bb.w);
        #pragma unroll
        for (int i = 0; i < 8; i++) {
            acc[i][0] = bp0; acc[i][1] = bp1; acc[i][2] = bp2; acc[i][3] = bp3;
        }
        #pragma unroll 4
        for (int k = 0; k < 64; k++) {
            ulonglong2 w0 = *(const ulonglong2*)&Ws[k * 64 + tc * 8];
            ulonglong2 w1 = *(const ulonglong2*)&Ws[k * 64 + tc * 8 + 4];
            float4 h0 = *(const float4*)&hs[k * 68 + tn * 8];
            float4 h1 = *(const float4*)&hs[k * 68 + tn * 8 + 4];
            #pragma unroll
            for (int i = 0; i < 8; i++) {
                float hv = (i < 4) ? (&h0.x)[i] : (&h1.x)[i - 4];
                unsigned long long h2 = pack2(hv, hv);
                FMA2(acc[i][0], h2, w0.x);
                FMA2(acc[i][1], h2, w0.y);
                FMA2(acc[i][2], h2, w1.x);
                FMA2(acc[i][3], h2, w1.y);
            }
        }
    }
    __syncthreads();   // layer-1 reads of hs AND Ws complete

    // Unpack + ReLU; transposed writeback hs[col][node]; swap W1 -> W2.
    #pragma unroll
    for (int i = 0; i < 8; i++) {
        #pragma unroll
        for (int p = 0; p < 4; p++) {
            float lo, hi;
            unpack2(acc[i][p], lo, hi);
            av[i][2 * p]     = fmaxf(lo, 0.f);
            av[i][2 * p + 1] = fmaxf(hi, 0.f);
        }
    }
    #pragma unroll
    for (int j = 0; j < 8; j++) {
        int c = tc * 8 + j;
        *(float4*)&hs[c * 68 + tn * 8] =
            make_float4(av[0][j], av[1][j], av[2][j], av[3][j]);
        *(float4*)&hs[c * 68 + tn * 8 + 4] =
            make_float4(av[4][j], av[5][j], av[6][j], av[7][j]);
    }
    for (int i = tid; i < 1024; i += 64)
        ((float4*)Ws)[i] = ((const float4*)W2)[i];
    __syncthreads();

    // ================= Layer 2: h2 = h1 @ W2 + b2 =================
    {
        float4 ba = *(const float4*)&b2s[tc * 8];
        float4 bb = *(const float4*)&b2s[tc * 8 + 4];
        unsigned long long bp0 = pack2(ba.x, ba.y), bp1 = pack2(ba.z, ba.w);
        unsigned long long bp2 = pack2(bb.x, bb.y), bp3 = pack2(bb.z, bb.w);
        #pragma unroll
        for (int i = 0; i < 8; i++) {
            acc[i][0] = bp0; acc[i][1] = bp1; acc[i][2] = bp2; acc[i][3] = bp3;
        }
        #pragma unroll 4
        for (int k = 0; k < 64; k++) {
            ulonglong2 w0 = *(const ulonglong2*)&Ws[k * 64 + tc * 8];
            ulonglong2 w1 = *(const ulonglong2*)&Ws[k * 64 + tc * 8 + 4];
            float4 h0 = *(const float4*)&hs[k * 68 + tn * 8];
            float4 h1 = *(const float4*)&hs[k * 68 + tn * 8 + 4];
            #pragma unroll
            for (int i = 0; i < 8; i++) {
                float hv = (i < 4) ? (&h0.x)[i] : (&h1.x)[i - 4];
                unsigned long long h2 = pack2(hv, hv);
                FMA2(acc[i][0], h2, w0.x);
                FMA2(acc[i][1], h2, w0.y);
                FMA2(acc[i][2], h2, w1.x);
                FMA2(acc[i][3], h2, w1.y);
            }
        }
    }

    // Epilogue: out = x + relu(h2). Thread owns f4 chunks tc*2 and tc*2+1
    // for nodes tn*8 .. tn*8+7.
    #pragma unroll
    for (int i = 0; i < 8; i++) {
        #pragma unroll
        for (int p = 0; p < 4; p++) {
            float lo, hi;
            unpack2(acc[i][p], lo, hi);
            av[i][2 * p]     = fmaxf(lo, 0.f);
            av[i][2 * p + 1] = fmaxf(hi, 0.f);
        }
    }
    #pragma unroll
    for (int i = 0; i < 8; i++) {
        int node = node0 + tn * 8 + i;
        if (node < N) {
            float4 xv0 = ((const float4*)x)[(size_t)node * 16 + tc * 2];
            float4 xv1 = ((const float4*)x)[(size_t)node * 16 + tc * 2 + 1];
            ((float4*)out)[(size_t)node * 16 + tc * 2] =
                make_float4(xv0.x + av[i][0], xv0.y + av[i][1],
                            xv0.z + av[i][2], xv0.w + av[i][3]);
            ((float4*)out)[(size_t)node * 16 + tc * 2 + 1] =
                make_float4(xv1.x + av[i][4], xv1.y + av[i][5],
                            xv1.z + av[i][6], xv1.w + av[i][7]);
        }
    }
}

// ---------------------------------------------------------------------------
// Launch
// ---------------------------------------------------------------------------
extern "C" void kernel_launch(void* const* d_in, const int* in_sizes, int n_in,
                              void* d_out, int out_size) {
    const float* x   = (const float*)d_in[0];
    const int*   ei  = (const int*)d_in[1];
    const float* W1  = (const float*)d_in[2];
    const float* b1  = (const float*)d_in[3];
    const float* W2  = (const float*)d_in[4];
    const float* b2  = (const float*)d_in[5];
    float* out = (float*)d_out;

    int N = in_sizes[0] / DIM;       // 100000
    int E = in_sizes[1] / 2;         // 1600000
    const int* src = ei;
    const int* dst = ei + E;

    // 1. init accumulator with x
    int n4 = N * (DIM / 4);
    init_kernel<<<(n4 + 255) / 256, 256>>>(x, n4);

    // 2. scatter-add neighbor features
    long long threads = (long long)E * 16;
    int sblocks = (int)((threads + 255) / 256);
    scatter_kernel<<<sblocks, 256>>>(x, src, dst, E);

    // 3. fused MLP + residual
    mlp_kernel<<<(N + 63) / 64, 64>>>(x, W1, b1, W2, b2, out, N);
}

// round 7
// speedup vs baseline: 1.2570x; 1.2570x over previous
#include <cuda_runtime.h>
#include <cuda_bf16.h>

#define DIM 64
#define NODES_MAX 100000
#define EDGES_MAX 1600000
#define NB_MAX 128   // >= ceil(NODES_MAX/1024)

// Allocation-free scratch (__device__ globals).
__device__ float g_agg[(size_t)NODES_MAX * DIM];   // h = x + sum(neighbors)
__device__ int   g_count[NODES_MAX];               // histogram -> fill cursor
__device__ int   g_start[NODES_MAX + 1];           // CSR row starts
__device__ int   g_csr[EDGES_MAX];                 // src per bucketed edge
__device__ int   g_bsum[NB_MAX];                   // per-block sums -> offsets

// ---------------------------------------------------------------------------
// 1. zero per-node counters
// ---------------------------------------------------------------------------
__global__ void zero_count_kernel(int N) {
    int i = blockIdx.x * blockDim.x + threadIdx.x;
    if (i < N) g_count[i] = 0;
}

// ---------------------------------------------------------------------------
// 2. histogram of dst
// ---------------------------------------------------------------------------
__global__ void hist_kernel(const int* __restrict__ dst, int E) {
    int i = blockIdx.x * blockDim.x + threadIdx.x;
    if (i < E) atomicAdd(&g_count[dst[i]], 1);
}

// ---------------------------------------------------------------------------
// 3a. per-block exclusive scan (coalesced), block totals -> g_bsum
// ---------------------------------------------------------------------------
__global__ __launch_bounds__(1024) void scan_local_kernel(int N) {
    __shared__ int sd[1024];
    int t = threadIdx.x;
    int i = blockIdx.x * 1024 + t;
    int v = (i < N) ? g_count[i] : 0;
    sd[t] = v;
    __syncthreads();
    #pragma unroll
    for (int off = 1; off < 1024; off <<= 1) {
        int u = (t >= off) ? sd[t - off] : 0;
        __syncthreads();
        sd[t] += u;
        __syncthreads();
    }
    if (i < N) g_start[i] = sd[t] - v;          // exclusive within block
    if (t == 1023) g_bsum[blockIdx.x] = sd[t];  // block total
}

// ---------------------------------------------------------------------------
// 3b. scan the block totals (single tiny block)
// ---------------------------------------------------------------------------
__global__ __launch_bounds__(NB_MAX) void scan_bsum_kernel(int nb) {
    __shared__ int sd[NB_MAX];
    int t = threadIdx.x;
    int v = (t < nb) ? g_bsum[t] : 0;
    sd[t] = v;
    __syncthreads();
    #pragma unroll
    for (int off = 1; off < NB_MAX; off <<= 1) {
        int u = (t >= off) ? sd[t - off] : 0;
        __syncthreads();
        sd[t] += u;
        __syncthreads();
    }
    if (t < nb) g_bsum[t] = sd[t] - v;          // exclusive block offsets
}

// ---------------------------------------------------------------------------
// 3c. add block offsets; init fill cursors to row starts; set g_start[N]=E
// ---------------------------------------------------------------------------
__global__ __launch_bounds__(1024) void finalize_kernel(int N, int E) {
    int i = blockIdx.x * 1024 + threadIdx.x;
    if (i < N) {
        int st = g_start[i] + g_bsum[blockIdx.x];
        g_start[i] = st;
        g_count[i] = st;                        // cursor
    }
    if (i == 0) g_start[N] = E;
}

// ---------------------------------------------------------------------------
// 4. fill CSR buckets: csr[cursor[d]++] = src  (cursor pre-offset to start)
// ---------------------------------------------------------------------------
__global__ void fill_kernel(const int* __restrict__ src,
                            const int* __restrict__ dst, int E) {
    int i = blockIdx.x * blockDim.x + threadIdx.x;
    if (i < E) {
        int pos = atomicAdd(&g_count[dst[i]], 1);
        g_csr[pos] = src[i];
    }
}

// ---------------------------------------------------------------------------
// 5. pull-gather: one warp per node. 16 lanes = float4 chunks, 2 neighbor
// slots; inner loop unrolled x2 -> 4 independent x-loads in flight per warp.
// Writes h = x[n] + sum(neighbors) with one coalesced 256B store. No atomics.
// ---------------------------------------------------------------------------
__global__ __launch_bounds__(256) void gather_kernel(const float* __restrict__ x,
                                                     int N) {
    int warp = (blockIdx.x * blockDim.x + threadIdx.x) >> 5;
    if (warp >= N) return;
    const int lane = threadIdx.x & 31;
    const int c    = lane & 15;     // float4 chunk
    const int slot = lane >> 4;     // 0/1

    const float4* x4 = (const float4*)x;
    const int n = warp;
    const int s = g_start[n];
    const int e = g_start[n + 1];

    float4 a = make_float4(0.f, 0.f, 0.f, 0.f);
    int j = s + slot;
    // slot handles j = s+slot, s+slot+2, ...; unrolled by 2 (stride 4)
    for (; j + 2 < e; j += 4) {
        int nb0 = __ldg(&g_csr[j]);
        int nb1 = __ldg(&g_csr[j + 2]);
        float4 v0 = __ldg(&x4[(size_t)nb0 * 16 + c]);
        float4 v1 = __ldg(&x4[(size_t)nb1 * 16 + c]);
        a.x += v0.x + v1.x;
        a.y += v0.y + v1.y;
        a.z += v0.z + v1.z;
        a.w += v0.w + v1.w;
    }
    if (j < e) {
        int nb = __ldg(&g_csr[j]);
        float4 v = __ldg(&x4[(size_t)nb * 16 + c]);
        a.x += v.x; a.y += v.y; a.z += v.z; a.w += v.w;
    }

    // combine the two slots (lane l <-> l^16 hold the same chunk c)
    a.x += __shfl_xor_sync(0xffffffffu, a.x, 16);
    a.y += __shfl_xor_sync(0xffffffffu, a.y, 16);
    a.z += __shfl_xor_sync(0xffffffffu, a.z, 16);
    a.w += __shfl_xor_sync(0xffffffffu, a.w, 16);

    if (slot == 0) {
        float4 xv = x4[(size_t)n * 16 + c];
        ((float4*)g_agg)[(size_t)n * 16 + c] =
            make_float4(xv.x + a.x, xv.y + a.y, xv.z + a.z, xv.w + a.w);
    }
}

// ---------------------------------------------------------------------------
// 6. fused MLP per 64-node tile (round-5 version: 128 threads, 4n x 8c tiles).
// ---------------------------------------------------------------------------
__global__ __launch_bounds__(128) void mlp_kernel(const float* __restrict__ x,
                                                  const float* __restrict__ W1,
                                                  const float* __restrict__ b1,
                                                  const float* __restrict__ W2,
                                                  const float* __restrict__ b2,
                                                  float* __restrict__ out,
                                                  int N) {
    __shared__ float Ws[64 * 64];
    __shared__ float b1s[64];
    __shared__ float b2s[64];
    __shared__ float hs[64 * 68];   // feature-major: hs[f * 68 + n]

    const int tid = threadIdx.x;

    for (int i = tid; i < 1024; i += 128)
        ((float4*)Ws)[i] = ((const float4*)W1)[i];
    if (tid < 64) {
        b1s[tid] = b1[tid];
        b2s[tid] = b2[tid];
    }

    const int node0 = blockIdx.x * 64;

    for (int i = tid; i < 1024; i += 128) {
        int n  = i >> 4;
        int f4 = i & 15;
        int node = node0 + n;
        float4 v = (node < N) ? ((const float4*)g_agg)[(size_t)node * 16 + f4]
                              : make_float4(0.f, 0.f, 0.f, 0.f);
        int f = f4 * 4;
        hs[(f + 0) * 68 + n] = v.x;
        hs[(f + 1) * 68 + n] = v.y;
        hs[(f + 2) * 68 + n] = v.z;
        hs[(f + 3) * 68 + n] = v.w;
    }
    __syncthreads();

    const int tc = tid >> 4;   // 0..7  : cols  tc*8 .. tc*8+7
    const int tn = tid & 15;   // 0..15 : nodes tn*4 .. tn*4+3

    float acc[4][8];

    // ---------------- Layer 1 ----------------
    {
        float4 ba = *(const float4*)&b1s[tc * 8];
        float4 bb = *(const float4*)&b1s[tc * 8 + 4];
        #pragma unroll
        for (int i = 0; i < 4; i++) {
            acc[i][0] = ba.x; acc[i][1] = ba.y; acc[i][2] = ba.z; acc[i][3] = ba.w;
            acc[i][4] = bb.x; acc[i][5] = bb.y; acc[i][6] = bb.z; acc[i][7] = bb.w;
        }
        #pragma unroll 4
        for (int k = 0; k < 64; k++) {
            float4 w0 = *(const float4*)&Ws[k * 64 + tc * 8];
            float4 w1 = *(const float4*)&Ws[k * 64 + tc * 8 + 4];
            float4 hv = *(const float4*)&hs[k * 68 + tn * 4];
            #pragma unroll
            for (int i = 0; i < 4; i++) {
                float h = (&hv.x)[i];
                acc[i][0] += h * w0.x; acc[i][1] += h * w0.y;
                acc[i][2] += h * w0.z; acc[i][3] += h * w0.w;
                acc[i][4] += h * w1.x; acc[i][5] += h * w1.y;
                acc[i][6] += h * w1.z; acc[i][7] += h * w1.w;
            }
        }
    }
    __syncthreads();

    #pragma unroll
    for (int j = 0; j < 8; j++) {
        int c = tc * 8 + j;
        float4 sv = make_float4(fmaxf(acc[0][j], 0.f), fmaxf(acc[1][j], 0.f),
                                fmaxf(acc[2][j], 0.f), fmaxf(acc[3][j], 0.f));
        *(float4*)&hs[c * 68 + tn * 4] = sv;
    }
    for (int i = tid; i < 1024; i += 128)
        ((float4*)Ws)[i] = ((const float4*)W2)[i];
    __syncthreads();

    // ---------------- Layer 2 ----------------
    {
        float4 ba = *(const float4*)&b2s[tc * 8];
        float4 bb = *(const float4*)&b2s[tc * 8 + 4];
        #pragma unroll
        for (int i = 0; i < 4; i++) {
            acc[i][0] = ba.x; acc[i][1] = ba.y; acc[i][2] = ba.z; acc[i][3] = ba.w;
            acc[i][4] = bb.x; acc[i][5] = bb.y; acc[i][6] = bb.z; acc[i][7] = bb.w;
        }
        #pragma unroll 4
        for (int k = 0; k < 64; k++) {
            float4 w0 = *(const float4*)&Ws[k * 64 + tc * 8];
            float4 w1 = *(const float4*)&Ws[k * 64 + tc * 8 + 4];
            float4 hv = *(const float4*)&hs[k * 68 + tn * 4];
            #pragma unroll
            for (int i = 0; i < 4; i++) {
                float h = (&hv.x)[i];
                acc[i][0] += h * w0.x; acc[i][1] += h * w0.y;
                acc[i][2] += h * w0.z; acc[i][3] += h * w0.w;
                acc[i][4] += h * w1.x; acc[i][5] += h * w1.y;
                acc[i][6] += h * w1.z; acc[i][7] += h * w1.w;
            }
        }
    }

    #pragma unroll
    for (int i = 0; i < 4; i++) {
        int node = node0 + tn * 4 + i;
        if (node < N) {
            float4 xv0 = ((const float4*)x)[(size_t)node * 16 + tc * 2];
            float4 xv1 = ((const float4*)x)[(size_t)node * 16 + tc * 2 + 1];
            ((float4*)out)[(size_t)node * 16 + tc * 2] =
                make_float4(xv0.x + fmaxf(acc[i][0], 0.f),
                            xv0.y + fmaxf(acc[i][1], 0.f),
                            xv0.z + fmaxf(acc[i][2], 0.f),
                            xv0.w + fmaxf(acc[i][3], 0.f));
            ((float4*)out)[(size_t)node * 16 + tc * 2 + 1] =
                make_float4(xv1.x + fmaxf(acc[i][4], 0.f),
                            xv1.y + fmaxf(acc[i][5], 0.f),
                            xv1.z + fmaxf(acc[i][6], 0.f),
                            xv1.w + fmaxf(acc[i][7], 0.f));
        }
    }
}

// ---------------------------------------------------------------------------
// Launch
// ---------------------------------------------------------------------------
extern "C" void kernel_launch(void* const* d_in, const int* in_sizes, int n_in,
                              void* d_out, int out_size) {
    const float* x   = (const float*)d_in[0];
    const int*   ei  = (const int*)d_in[1];
    const float* W1  = (const float*)d_in[2];
    const float* b1  = (const float*)d_in[3];
    const float* W2  = (const float*)d_in[4];
    const float* b2  = (const float*)d_in[5];
    float* out = (float*)d_out;

    int N = in_sizes[0] / DIM;       // 100000
    int E = in_sizes[1] / 2;         // 1600000
    const int* src = ei;
    const int* dst = ei + E;

    int nb = (N + 1023) / 1024;      // 98 <= NB_MAX

    zero_count_kernel<<<(N + 255) / 256, 256>>>(N);
    hist_kernel<<<(E + 255) / 256, 256>>>(dst, E);
    scan_local_kernel<<<nb, 1024>>>(N);
    scan_bsum_kernel<<<1, NB_MAX>>>(nb);
    finalize_kernel<<<nb, 1024>>>(N, E);
    fill_kernel<<<(E + 255) / 256, 256>>>(src, dst, E);

    // one warp per node
    gather_kernel<<<(N * 32 + 255) / 256, 256>>>(x, N);

    mlp_kernel<<<(N + 63) / 64, 128>>>(x, W1, b1, W2, b2, out, N);
}

// round 9
// speedup vs baseline: 1.4310x; 1.1385x over previous
#include <cuda_runtime.h>
#include <cuda_bf16.h>
#include <cstdint>
#include <cstring>

#define DIM 64
#define NODES_MAX 100000
#define EDGES_MAX 1600000
#define NB_MAX 128   // >= ceil(NODES_MAX/1024)

// Allocation-free scratch (__device__ globals).
__device__ float g_agg[(size_t)NODES_MAX * DIM];   // h = x + sum(neighbors)
__device__ int   g_count[NODES_MAX];               // histogram -> fill cursor
__device__ int   g_start[NODES_MAX + 1];           // CSR row starts
__device__ int   g_csr[EDGES_MAX];                 // src per bucketed edge
__device__ int   g_bsum[NB_MAX];                   // per-block sums -> offsets

// ===========================================================================
// CSR build + gather (unchanged, known-good)
// ===========================================================================
__global__ void zero_count_kernel(int N) {
    int i = blockIdx.x * blockDim.x + threadIdx.x;
    if (i < N) g_count[i] = 0;
}

__global__ void hist_kernel(const int* __restrict__ dst, int E) {
    int i = blockIdx.x * blockDim.x + threadIdx.x;
    if (i < E) atomicAdd(&g_count[dst[i]], 1);
}

__global__ __launch_bounds__(1024) void scan_local_kernel(int N) {
    __shared__ int sd[1024];
    int t = threadIdx.x;
    int i = blockIdx.x * 1024 + t;
    int v = (i < N) ? g_count[i] : 0;
    sd[t] = v;
    __syncthreads();
    #pragma unroll
    for (int off = 1; off < 1024; off <<= 1) {
        int u = (t >= off) ? sd[t - off] : 0;
        __syncthreads();
        sd[t] += u;
        __syncthreads();
    }
    if (i < N) g_start[i] = sd[t] - v;
    if (t == 1023) g_bsum[blockIdx.x] = sd[t];
}

__global__ __launch_bounds__(NB_MAX) void scan_bsum_kernel(int nb) {
    __shared__ int sd[NB_MAX];
    int t = threadIdx.x;
    int v = (t < nb) ? g_bsum[t] : 0;
    sd[t] = v;
    __syncthreads();
    #pragma unroll
    for (int off = 1; off < NB_MAX; off <<= 1) {
        int u = (t >= off) ? sd[t - off] : 0;
        __syncthreads();
        sd[t] += u;
        __syncthreads();
    }
    if (t < nb) g_bsum[t] = sd[t] - v;
}

__global__ __launch_bounds__(1024) void finalize_kernel(int N, int E) {
    int i = blockIdx.x * 1024 + threadIdx.x;
    if (i < N) {
        int st = g_start[i] + g_bsum[blockIdx.x];
        g_start[i] = st;
        g_count[i] = st;
    }
    if (i == 0) g_start[N] = E;
}

__global__ void fill_kernel(const int* __restrict__ src,
                            const int* __restrict__ dst, int E) {
    int i = blockIdx.x * blockDim.x + threadIdx.x;
    if (i < E) {
        int pos = atomicAdd(&g_count[dst[i]], 1);
        g_csr[pos] = src[i];
    }
}

__global__ __launch_bounds__(256) void gather_kernel(const float* __restrict__ x,
                                                     int N) {
    int warp = (blockIdx.x * blockDim.x + threadIdx.x) >> 5;
    if (warp >= N) return;
    const int lane = threadIdx.x & 31;
    const int c    = lane & 15;
    const int slot = lane >> 4;

    const float4* x4 = (const float4*)x;
    const int n = warp;
    const int s = g_start[n];
    const int e = g_start[n + 1];

    float4 a = make_float4(0.f, 0.f, 0.f, 0.f);
    int j = s + slot;
    for (; j + 2 < e; j += 4) {
        int nb0 = __ldg(&g_csr[j]);
        int nb1 = __ldg(&g_csr[j + 2]);
        float4 v0 = __ldg(&x4[(size_t)nb0 * 16 + c]);
        float4 v1 = __ldg(&x4[(size_t)nb1 * 16 + c]);
        a.x += v0.x + v1.x;
        a.y += v0.y + v1.y;
        a.z += v0.z + v1.z;
        a.w += v0.w + v1.w;
    }
    if (j < e) {
        int nb = __ldg(&g_csr[j]);
        float4 v = __ldg(&x4[(size_t)nb * 16 + c]);
        a.x += v.x; a.y += v.y; a.z += v.z; a.w += v.w;
    }

    a.x += __shfl_xor_sync(0xffffffffu, a.x, 16);
    a.y += __shfl_xor_sync(0xffffffffu, a.y, 16);
    a.z += __shfl_xor_sync(0xffffffffu, a.z, 16);
    a.w += __shfl_xor_sync(0xffffffffu, a.w, 16);

    if (slot == 0) {
        float4 xv = x4[(size_t)n * 16 + c];
        ((float4*)g_agg)[(size_t)n * 16 + c] =
            make_float4(xv.x + a.x, xv.y + a.y, xv.z + a.z, xv.w + a.w);
    }
}

// ===========================================================================
// Tensor-core MLP via mma.sync m16n8k16 bf16 (baseline sm_80+ PTX).
// Split-bf16: D = Ah@Bh + Ah@Bl + Al@Bh  (error ~2^-17).
// Block: 128 nodes, 256 threads = 8 warps; warp w owns rows w*16..w*16+15.
// Layer-2 A fragments built in-register from layer-1 accumulators
// (C-fragment layout == A-fragment layout), so one __syncthreads total.
// ===========================================================================
__device__ __forceinline__ uint32_t smem_u32(const void* p) {
    uint32_t a;
    asm("{ .reg .u64 t; cvta.to.shared.u64 t, %1; cvt.u32.u64 %0, t; }"
        : "=r"(a) : "l"(p));
    return a;
}

__device__ __forceinline__ void ldm4(uint32_t* f, uint32_t addr) {
    asm volatile("ldmatrix.sync.aligned.m8n8.x4.shared.b16 {%0,%1,%2,%3}, [%4];"
                 : "=r"(f[0]), "=r"(f[1]), "=r"(f[2]), "=r"(f[3]) : "r"(addr));
}

__device__ __forceinline__ void mma16816(float* d, const uint32_t* a,
                                         uint32_t b0, uint32_t b1) {
    asm volatile(
        "mma.sync.aligned.m16n8k16.row.col.f32.bf16.bf16.f32 "
        "{%0,%1,%2,%3}, {%4,%5,%6,%7}, {%8,%9}, {%0,%1,%2,%3};"
        : "+f"(d[0]), "+f"(d[1]), "+f"(d[2]), "+f"(d[3])
        : "r"(a[0]), "r"(a[1]), "r"(a[2]), "r"(a[3]), "r"(b0), "r"(b1));
}

__device__ __forceinline__ uint32_t pack_bf(__nv_bfloat16 a, __nv_bfloat16 b) {
    __nv_bfloat162 t;
    t.x = a; t.y = b;
    uint32_t r;
    memcpy(&r, &t, 4);
    return r;
}

// split two fp32 into packed bf16 hi and lo parts
__device__ __forceinline__ void split2(float a, float b,
                                       uint32_t& hi, uint32_t& lo) {
    __nv_bfloat16 ah = __float2bfloat16_rn(a);
    __nv_bfloat16 bh = __float2bfloat16_rn(b);
    hi = pack_bf(ah, bh);
    lo = pack_bf(__float2bfloat16_rn(a - __bfloat162float(ah)),
                 __float2bfloat16_rn(b - __bfloat162float(bh)));
}

// SMEM layout (byte offsets). Rows padded to 144 B (9 x 16B) -> ldmatrix
// addresses walk bank groups conflict-free.
#define STRIDE 144
#define A_HI_OFF 0
#define A_LO_OFF 18432
#define B1H_OFF  36864
#define B1L_OFF  46080
#define B2H_OFF  55296
#define B2L_OFF  64512
#define MLP_SMEM 73728

__global__ __launch_bounds__(256) void mlp_tc_kernel(const float* __restrict__ x,
                                                     const float* __restrict__ W1,
                                                     const float* __restrict__ b1,
                                                     const float* __restrict__ W2,
                                                     const float* __restrict__ b2,
                                                     float* __restrict__ out,
                                                     int N) {
    extern __shared__ char sm[];
    const uint32_t sbase = smem_u32(sm);
    const int tid  = threadIdx.x;
    const int node0 = blockIdx.x * 128;

    // ---- Stage A: h = g_agg rows -> split bf16, row-major stride 144 B ----
    for (int i = tid; i < 2048; i += 256) {
        int m  = i >> 4;
        int f4 = i & 15;
        int node = node0 + m;
        float4 v = (node < N) ? ((const float4*)g_agg)[(size_t)node * 16 + f4]
                              : make_float4(0.f, 0.f, 0.f, 0.f);
        uint32_t h0, l0, h1, l1;
        split2(v.x, v.y, h0, l0);
        split2(v.z, v.w, h1, l1);
        uint32_t off = (uint32_t)m * STRIDE + (uint32_t)f4 * 8;
        *(uint2*)(sm + A_HI_OFF + off) = make_uint2(h0, h1);
        *(uint2*)(sm + A_LO_OFF + off) = make_uint2(l0, l1);
    }

    // ---- Stage B: W^T[n][k] = W[k][n], split bf16, stride 144 B ----
    for (int i = tid; i < 1024; i += 256) {
        int k  = i >> 4;
        int n0 = (i & 15) * 4;
        float4 w1v = ((const float4*)W1)[i];
        float4 w2v = ((const float4*)W2)[i];
        #pragma unroll
        for (int j = 0; j < 4; j++) {
            uint32_t off = (uint32_t)(n0 + j) * STRIDE + (uint32_t)k * 2;
            float v1 = (&w1v.x)[j];
            __nv_bfloat16 h1b = __float2bfloat16_rn(v1);
            *(__nv_bfloat16*)(sm + B1H_OFF + off) = h1b;
            *(__nv_bfloat16*)(sm + B1L_OFF + off) =
                __float2bfloat16_rn(v1 - __bfloat162float(h1b));
            float v2 = (&w2v.x)[j];
            __nv_bfloat16 h2b = __float2bfloat16_rn(v2);
            *(__nv_bfloat16*)(sm + B2H_OFF + off) = h2b;
            *(__nv_bfloat16*)(sm + B2L_OFF + off) =
                __float2bfloat16_rn(v2 - __bfloat162float(h2b));
        }
    }
    __syncthreads();

    const int w    = tid >> 5;     // warp = m-tile (16 rows)
    const int lane = tid & 31;
    const int g    = lane >> 2;    // row in fragment
    const int t    = lane & 3;     // col pair index
    const int q    = lane >> 3;    // ldmatrix quadrant
    const int r    = lane & 7;

    // ldmatrix lane addresses (byte offsets); + kk*32 per k-step
    const uint32_t aoff = (uint32_t)(w * 16 + (q & 1) * 8 + r) * STRIDE
                        + (uint32_t)(q >> 1) * 16;
    // B: reg0 = b0(n=2p), reg1 = b1(n=2p), reg2 = b0(n=2p+1), reg3 = b1(n=2p+1)
    // row add for n-tile parity = (q>>1)*8, col add for k half = (q&1)*16
    const uint32_t boff0 = (uint32_t)((q >> 1) * 8 + r) * STRIDE
                         + (uint32_t)(q & 1) * 16;

    float acc1[8][4];
    #pragma unroll
    for (int n = 0; n < 8; n++)
        #pragma unroll
        for (int j = 0; j < 4; j++) acc1[n][j] = 0.f;

    // ================= Layer 1 =================
    #pragma unroll
    for (int kk = 0; kk < 4; kk++) {
        uint32_t ah[4], al[4];
        ldm4(ah, sbase + A_HI_OFF + aoff + kk * 32);
        ldm4(al, sbase + A_LO_OFF + aoff + kk * 32);
        #pragma unroll
        for (int p = 0; p < 4; p++) {
            uint32_t bo = boff0 + (uint32_t)p * 16 * STRIDE + kk * 32;
            uint32_t bh[4], bl[4];
            ldm4(bh, sbase + B1H_OFF + bo);
            ldm4(bl, sbase + B1L_OFF + bo);
            mma16816(acc1[2 * p],     ah, bh[0], bh[1]);
            mma16816(acc1[2 * p],     ah, bl[0], bl[1]);
            mma16816(acc1[2 * p],     al, bh[0], bh[1]);
            mma16816(acc1[2 * p + 1], ah, bh[2], bh[3]);
            mma16816(acc1[2 * p + 1], ah, bl[2], bl[3]);
            mma16816(acc1[2 * p + 1], al, bh[2], bh[3]);
        }
    }

    // ================= Layer 2 (A fragments from registers) =================
    float acc2[8][4];
    #pragma unroll
    for (int n = 0; n < 8; n++)
        #pragma unroll
        for (int j = 0; j < 4; j++) acc2[n][j] = 0.f;

    #pragma unroll
    for (int kk = 0; kk < 4; kk++) {
        // layer-1 n-tiles 2kk, 2kk+1 become layer-2 k dims 0-7, 8-15
        uint32_t ah[4], al[4];
        {
            int nt = 2 * kk;
            float bb0 = __ldg(&b1[nt * 8 + 2 * t]);
            float bb1 = __ldg(&b1[nt * 8 + 2 * t + 1]);
            split2(fmaxf(acc1[nt][0] + bb0, 0.f),
                   fmaxf(acc1[nt][1] + bb1, 0.f), ah[0], al[0]);
            split2(fmaxf(acc1[nt][2] + bb0, 0.f),
                   fmaxf(acc1[nt][3] + bb1, 0.f), ah[1], al[1]);
            nt = 2 * kk + 1;
            bb0 = __ldg(&b1[nt * 8 + 2 * t]);
            bb1 = __ldg(&b1[nt * 8 + 2 * t + 1]);
            split2(fmaxf(acc1[nt][0] + bb0, 0.f),
                   fmaxf(acc1[nt][1] + bb1, 0.f), ah[2], al[2]);
            split2(fmaxf(acc1[nt][2] + bb0, 0.f),
                   fmaxf(acc1[nt][3] + bb1, 0.f), ah[3], al[3]);
        }
        #pragma unroll
        for (int p = 0; p < 4; p++) {
            uint32_t bo = boff0 + (uint32_t)p * 16 * STRIDE + kk * 32;
            uint32_t bh[4], bl[4];
            ldm4(bh, sbase + B2H_OFF + bo);
            ldm4(bl, sbase + B2L_OFF + bo);
            mma16816(acc2[2 * p],     ah, bh[0], bh[1]);
            mma16816(acc2[2 * p],     ah, bl[0], bl[1]);
            mma16816(acc2[2 * p],     al, bh[0], bh[1]);
            mma16816(acc2[2 * p + 1], ah, bh[2], bh[3]);
            mma16816(acc2[2 * p + 1], ah, bl[2], bl[3]);
            mma16816(acc2[2 * p + 1], al, bh[2], bh[3]);
        }
    }

    // ================= Epilogue: out = x + relu(acc2 + b2) =================
    const int nodeA = node0 + w * 16 + g;
    const int nodeB = nodeA + 8;
    #pragma unroll
    for (int nt = 0; nt < 8; nt++) {
        int col = nt * 8 + 2 * t;
        float bb0 = __ldg(&b2[col]);
        float bb1 = __ldg(&b2[col + 1]);
        if (nodeA < N) {
            const float2 xv = *(const float2*)&x[(size_t)nodeA * 64 + col];
            float2 o;
            o.x = xv.x + fmaxf(acc2[nt][0] + bb0, 0.f);
            o.y = xv.y + fmaxf(acc2[nt][1] + bb1, 0.f);
            *(float2*)&out[(size_t)nodeA * 64 + col] = o;
        }
        if (nodeB < N) {
            const float2 xv = *(const float2*)&x[(size_t)nodeB * 64 + col];
            float2 o;
            o.x = xv.x + fmaxf(acc2[nt][2] + bb0, 0.f);
            o.y = xv.y + fmaxf(acc2[nt][3] + bb1, 0.f);
            *(float2*)&out[(size_t)nodeB * 64 + col] = o;
        }
    }
}

// ===========================================================================
// Launch
// ===========================================================================
extern "C" void kernel_launch(void* const* d_in, const int* in_sizes, int n_in,
                              void* d_out, int out_size) {
    const float* x   = (const float*)d_in[0];
    const int*   ei  = (const int*)d_in[1];
    const float* W1  = (const float*)d_in[2];
    const float* b1  = (const float*)d_in[3];
    const float* W2  = (const float*)d_in[4];
    const float* b2  = (const float*)d_in[5];
    float* out = (float*)d_out;

    int N = in_sizes[0] / DIM;       // 100000
    int E = in_sizes[1] / 2;         // 1600000
    const int* src = ei;
    const int* dst = ei + E;

    int nb = (N + 1023) / 1024;      // 98 <= NB_MAX

    zero_count_kernel<<<(N + 255) / 256, 256>>>(N);
    hist_kernel<<<(E + 255) / 256, 256>>>(dst, E);
    scan_local_kernel<<<nb, 1024>>>(N);
    scan_bsum_kernel<<<1, NB_MAX>>>(nb);
    finalize_kernel<<<nb, 1024>>>(N, E);
    fill_kernel<<<(E + 255) / 256, 256>>>(src, dst, E);
    gather_kernel<<<(N * 32 + 255) / 256, 256>>>(x, N);

    static bool smem_set = false;
    if (!smem_set) {
        cudaFuncSetAttribute(mlp_tc_kernel,
                             cudaFuncAttributeMaxDynamicSharedMemorySize,
                             MLP_SMEM);
        smem_set = true;
    }
    mlp_tc_kernel<<<(N + 127) / 128, 256, MLP_SMEM>>>(x, W1, b1, W2, b2, out, N);
}

// round 10
// speedup vs baseline: 1.4821x; 1.0357x over previous
#include <cuda_runtime.h>
#include <cuda_bf16.h>
#include <cstdint>
#include <cstring>

#define DIM 64
#define NODES_MAX 100000
#define EDGES_MAX 1600000

// Allocation-free scratch (__device__ globals).
__device__ float g_agg[(size_t)NODES_MAX * DIM];   // h = x + sum(neighbors)
__device__ int   g_count[NODES_MAX];               // node degree (persists)
__device__ int   g_start[NODES_MAX];               // CSR bucket starts
__device__ int   g_csr[EDGES_MAX];                 // src per bucketed edge
__device__ int   g_rank[EDGES_MAX];                // edge rank within bucket
__device__ int   g_cursor;                         // global bucket allocator

// ===========================================================================
// 1. zero degree counters + global cursor
// ===========================================================================
__global__ void zero_count_kernel(int N) {
    int i = blockIdx.x * blockDim.x + threadIdx.x;
    if (i < N) g_count[i] = 0;
    if (i == 0) g_cursor = 0;
}

// ===========================================================================
// 2. histogram of dst; the returned old value IS the edge's bucket rank
// ===========================================================================
__global__ void hist_rank_kernel(const int* __restrict__ dst, int E) {
    int i = blockIdx.x * blockDim.x + threadIdx.x;
    if (i < E) g_rank[i] = atomicAdd(&g_count[dst[i]], 1);
}

// ===========================================================================
// 3. one-pass scan: per-block local exclusive scan + atomic block base.
// Buckets are NOT in node order (base order is atomic-arrival order) — fine,
// gather uses start[n] + degree[n]. g_count (degree) is preserved.
// ===========================================================================
__global__ __launch_bounds__(1024) void scan_kernel(int N) {
    __shared__ int sd[1024];
    __shared__ int base_sh;
    int t = threadIdx.x;
    int i = blockIdx.x * 1024 + t;
    int v = (i < N) ? g_count[i] : 0;
    sd[t] = v;
    __syncthreads();
    #pragma unroll
    for (int off = 1; off < 1024; off <<= 1) {
        int u = (t >= off) ? sd[t - off] : 0;
        __syncthreads();
        sd[t] += u;
        __syncthreads();
    }
    if (t == 1023) base_sh = atomicAdd(&g_cursor, sd[1023]);
    __syncthreads();
    if (i < N) g_start[i] = base_sh + sd[t] - v;
}

// ===========================================================================
// 4. atomic-free fill: pos = start[dst] + rank
// ===========================================================================
__global__ void fill_kernel(const int* __restrict__ src,
                            const int* __restrict__ dst, int E) {
    int i = blockIdx.x * blockDim.x + threadIdx.x;
    if (i < E) {
        g_csr[g_start[dst[i]] + g_rank[i]] = src[i];
    }
}

// ===========================================================================
// 5. pull-gather (round-7 structure; bucket end = start + degree)
// ===========================================================================
__global__ __launch_bounds__(256) void gather_kernel(const float* __restrict__ x,
                                                     int N) {
    int warp = (blockIdx.x * blockDim.x + threadIdx.x) >> 5;
    if (warp >= N) return;
    const int lane = threadIdx.x & 31;
    const int c    = lane & 15;
    const int slot = lane >> 4;

    const float4* x4 = (const float4*)x;
    const int n = warp;
    const int s = g_start[n];
    const int e = s + g_count[n];

    float4 a = make_float4(0.f, 0.f, 0.f, 0.f);
    int j = s + slot;
    for (; j + 2 < e; j += 4) {
        int nb0 = __ldg(&g_csr[j]);
        int nb1 = __ldg(&g_csr[j + 2]);
        float4 v0 = __ldg(&x4[(size_t)nb0 * 16 + c]);
        float4 v1 = __ldg(&x4[(size_t)nb1 * 16 + c]);
        a.x += v0.x + v1.x;
        a.y += v0.y + v1.y;
        a.z += v0.z + v1.z;
        a.w += v0.w + v1.w;
    }
    if (j < e) {
        int nb = __ldg(&g_csr[j]);
        float4 v = __ldg(&x4[(size_t)nb * 16 + c]);
        a.x += v.x; a.y += v.y; a.z += v.z; a.w += v.w;
    }

    a.x += __shfl_xor_sync(0xffffffffu, a.x, 16);
    a.y += __shfl_xor_sync(0xffffffffu, a.y, 16);
    a.z += __shfl_xor_sync(0xffffffffu, a.z, 16);
    a.w += __shfl_xor_sync(0xffffffffu, a.w, 16);

    if (slot == 0) {
        float4 xv = x4[(size_t)n * 16 + c];
        ((float4*)g_agg)[(size_t)n * 16 + c] =
            make_float4(xv.x + a.x, xv.y + a.y, xv.z + a.z, xv.w + a.w);
    }
}

// ===========================================================================
// 6. Tensor-core MLP via mma.sync m16n8k16 bf16 (unchanged from round 9).
// Split-bf16: D = Ah@Bh + Ah@Bl + Al@Bh  (error ~2^-17).
// ===========================================================================
__device__ __forceinline__ uint32_t smem_u32(const void* p) {
    uint32_t a;
    asm("{ .reg .u64 t; cvta.to.shared.u64 t, %1; cvt.u32.u64 %0, t; }"
        : "=r"(a) : "l"(p));
    return a;
}

__device__ __forceinline__ void ldm4(uint32_t* f, uint32_t addr) {
    asm volatile("ldmatrix.sync.aligned.m8n8.x4.shared.b16 {%0,%1,%2,%3}, [%4];"
                 : "=r"(f[0]), "=r"(f[1]), "=r"(f[2]), "=r"(f[3]) : "r"(addr));
}

__device__ __forceinline__ void mma16816(float* d, const uint32_t* a,
                                         uint32_t b0, uint32_t b1) {
    asm volatile(
        "mma.sync.aligned.m16n8k16.row.col.f32.bf16.bf16.f32 "
        "{%0,%1,%2,%3}, {%4,%5,%6,%7}, {%8,%9}, {%0,%1,%2,%3};"
        : "+f"(d[0]), "+f"(d[1]), "+f"(d[2]), "+f"(d[3])
        : "r"(a[0]), "r"(a[1]), "r"(a[2]), "r"(a[3]), "r"(b0), "r"(b1));
}

__device__ __forceinline__ uint32_t pack_bf(__nv_bfloat16 a, __nv_bfloat16 b) {
    __nv_bfloat162 t;
    t.x = a; t.y = b;
    uint32_t r;
    memcpy(&r, &t, 4);
    return r;
}

__device__ __forceinline__ void split2(float a, float b,
                                       uint32_t& hi, uint32_t& lo) {
    __nv_bfloat16 ah = __float2bfloat16_rn(a);
    __nv_bfloat16 bh = __float2bfloat16_rn(b);
    hi = pack_bf(ah, bh);
    lo = pack_bf(__float2bfloat16_rn(a - __bfloat162float(ah)),
                 __float2bfloat16_rn(b - __bfloat162float(bh)));
}

#define STRIDE 144
#define A_HI_OFF 0
#define A_LO_OFF 18432
#define B1H_OFF  36864
#define B1L_OFF  46080
#define B2H_OFF  55296
#define B2L_OFF  64512
#define MLP_SMEM 73728

__global__ __launch_bounds__(256) void mlp_tc_kernel(const float* __restrict__ x,
                                                     const float* __restrict__ W1,
                                                     const float* __restrict__ b1,
                                                     const float* __restrict__ W2,
                                                     const float* __restrict__ b2,
                                                     float* __restrict__ out,
                                                     int N) {
    extern __shared__ char sm[];
    const uint32_t sbase = smem_u32(sm);
    const int tid  = threadIdx.x;
    const int node0 = blockIdx.x * 128;

    for (int i = tid; i < 2048; i += 256) {
        int m  = i >> 4;
        int f4 = i & 15;
        int node = node0 + m;
        float4 v = (node < N) ? ((const float4*)g_agg)[(size_t)node * 16 + f4]
                              : make_float4(0.f, 0.f, 0.f, 0.f);
        uint32_t h0, l0, h1, l1;
        split2(v.x, v.y, h0, l0);
        split2(v.z, v.w, h1, l1);
        uint32_t off = (uint32_t)m * STRIDE + (uint32_t)f4 * 8;
        *(uint2*)(sm + A_HI_OFF + off) = make_uint2(h0, h1);
        *(uint2*)(sm + A_LO_OFF + off) = make_uint2(l0, l1);
    }

    for (int i = tid; i < 1024; i += 256) {
        int k  = i >> 4;
        int n0 = (i & 15) * 4;
        float4 w1v = ((const float4*)W1)[i];
        float4 w2v = ((const float4*)W2)[i];
        #pragma unroll
        for (int j = 0; j < 4; j++) {
            uint32_t off = (uint32_t)(n0 + j) * STRIDE + (uint32_t)k * 2;
            float v1 = (&w1v.x)[j];
            __nv_bfloat16 h1b = __float2bfloat16_rn(v1);
            *(__nv_bfloat16*)(sm + B1H_OFF + off) = h1b;
            *(__nv_bfloat16*)(sm + B1L_OFF + off) =
                __float2bfloat16_rn(v1 - __bfloat162float(h1b));
            float v2 = (&w2v.x)[j];
            __nv_bfloat16 h2b = __float2bfloat16_rn(v2);
            *(__nv_bfloat16*)(sm + B2H_OFF + off) = h2b;
            *(__nv_bfloat16*)(sm + B2L_OFF + off) =
                __float2bfloat16_rn(v2 - __bfloat162float(h2b));
        }
    }
    __syncthreads();

    const int w    = tid >> 5;
    const int lane = tid & 31;
    const int g    = lane >> 2;
    const int t    = lane & 3;
    const int q    = lane >> 3;
    const int r    = lane & 7;

    const uint32_t aoff = (uint32_t)(w * 16 + (q & 1) * 8 + r) * STRIDE
                        + (uint32_t)(q >> 1) * 16;
    const uint32_t boff0 = (uint32_t)((q >> 1) * 8 + r) * STRIDE
                         + (uint32_t)(q & 1) * 16;

    float acc1[8][4];
    #pragma unroll
    for (int n = 0; n < 8; n++)
        #pragma unroll
        for (int j = 0; j < 4; j++) acc1[n][j] = 0.f;

    #pragma unroll
    for (int kk = 0; kk < 4; kk++) {
        uint32_t ah[4], al[4];
        ldm4(ah, sbase + A_HI_OFF + aoff + kk * 32);
        ldm4(al, sbase + A_LO_OFF + aoff + kk * 32);
        #pragma unroll
        for (int p = 0; p < 4; p++) {
            uint32_t bo = boff0 + (uint32_t)p * 16 * STRIDE + kk * 32;
            uint32_t bh[4], bl[4];
            ldm4(bh, sbase + B1H_OFF + bo);
            ldm4(bl, sbase + B1L_OFF + bo);
            mma16816(acc1[2 * p],     ah, bh[0], bh[1]);
            mma16816(acc1[2 * p],     ah, bl[0], bl[1]);
            mma16816(acc1[2 * p],     al, bh[0], bh[1]);
            mma16816(acc1[2 * p + 1], ah, bh[2], bh[3]);
            mma16816(acc1[2 * p + 1], ah, bl[2], bl[3]);
            mma16816(acc1[2 * p + 1], al, bh[2], bh[3]);
        }
    }

    float acc2[8][4];
    #pragma unroll
    for (int n = 0; n < 8; n++)
        #pragma unroll
        for (int j = 0; j < 4; j++) acc2[n][j] = 0.f;

    #pragma unroll
    for (int kk = 0; kk < 4; kk++) {
        uint32_t ah[4], al[4];
        {
            int nt = 2 * kk;
            float bb0 = __ldg(&b1[nt * 8 + 2 * t]);
            float bb1 = __ldg(&b1[nt * 8 + 2 * t + 1]);
            split2(fmaxf(acc1[nt][0] + bb0, 0.f),
                   fmaxf(acc1[nt][1] + bb1, 0.f), ah[0], al[0]);
            split2(fmaxf(acc1[nt][2] + bb0, 0.f),
                   fmaxf(acc1[nt][3] + bb1, 0.f), ah[1], al[1]);
            nt = 2 * kk + 1;
            bb0 = __ldg(&b1[nt * 8 + 2 * t]);
            bb1 = __ldg(&b1[nt * 8 + 2 * t + 1]);
            split2(fmaxf(acc1[nt][0] + bb0, 0.f),
                   fmaxf(acc1[nt][1] + bb1, 0.f), ah[2], al[2]);
            split2(fmaxf(acc1[nt][2] + bb0, 0.f),
                   fmaxf(acc1[nt][3] + bb1, 0.f), ah[3], al[3]);
        }
        #pragma unroll
        for (int p = 0; p < 4; p++) {
            uint32_t bo = boff0 + (uint32_t)p * 16 * STRIDE + kk * 32;
            uint32_t bh[4], bl[4];
            ldm4(bh, sbase + B2H_OFF + bo);
            ldm4(bl, sbase + B2L_OFF + bo);
            mma16816(acc2[2 * p],     ah, bh[0], bh[1]);
            mma16816(acc2[2 * p],     ah, bl[0], bl[1]);
            mma16816(acc2[2 * p],     al, bh[0], bh[1]);
            mma16816(acc2[2 * p + 1], ah, bh[2], bh[3]);
            mma16816(acc2[2 * p + 1], ah, bl[2], bl[3]);
            mma16816(acc2[2 * p + 1], al, bh[2], bh[3]);
        }
    }

    const int nodeA = node0 + w * 16 + g;
    const int nodeB = nodeA + 8;
    #pragma unroll
    for (int nt = 0; nt < 8; nt++) {
        int col = nt * 8 + 2 * t;
        float bb0 = __ldg(&b2[col]);
        float bb1 = __ldg(&b2[col + 1]);
        if (nodeA < N) {
            const float2 xv = *(const float2*)&x[(size_t)nodeA * 64 + col];
            float2 o;
            o.x = xv.x + fmaxf(acc2[nt][0] + bb0, 0.f);
            o.y = xv.y + fmaxf(acc2[nt][1] + bb1, 0.f);
            *(float2*)&out[(size_t)nodeA * 64 + col] = o;
        }
        if (nodeB < N) {
            const float2 xv = *(const float2*)&x[(size_t)nodeB * 64 + col];
            float2 o;
            o.x = xv.x + fmaxf(acc2[nt][2] + bb0, 0.f);
            o.y = xv.y + fmaxf(acc2[nt][3] + bb1, 0.f);
            *(float2*)&out[(size_t)nodeB * 64 + col] = o;
        }
    }
}

// ===========================================================================
// Launch (6 kernels)
// ===========================================================================
extern "C" void kernel_launch(void* const* d_in, const int* in_sizes, int n_in,
                              void* d_out, int out_size) {
    const float* x   = (const float*)d_in[0];
    const int*   ei  = (const int*)d_in[1];
    const float* W1  = (const float*)d_in[2];
    const float* b1  = (const float*)d_in[3];
    const float* W2  = (const float*)d_in[4];
    const float* b2  = (const float*)d_in[5];
    float* out = (float*)d_out;

    int N = in_sizes[0] / DIM;       // 100000
    int E = in_sizes[1] / 2;         // 1600000
    const int* src = ei;
    const int* dst = ei + E;

    int nb = (N + 1023) / 1024;

    zero_count_kernel<<<(N + 255) / 256, 256>>>(N);
    hist_rank_kernel<<<(E + 255) / 256, 256>>>(dst, E);
    scan_kernel<<<nb, 1024>>>(N);
    fill_kernel<<<(E + 255) / 256, 256>>>(src, dst, E);
    gather_kernel<<<(N * 32 + 255) / 256, 256>>>(x, N);

    static bool smem_set = false;
    if (!smem_set) {
        cudaFuncSetAttribute(mlp_tc_kernel,
                             cudaFuncAttributeMaxDynamicSharedMemorySize,
                             MLP_SMEM);
        smem_set = true;
    }
    mlp_tc_kernel<<<(N + 127) / 128, 256, MLP_SMEM>>>(x, W1, b1, W2, b2, out, N);
}